// round 1
// baseline (speedup 1.0000x reference)
#include <cuda_runtime.h>
#include <math.h>

#define T_  512
#define B_  256
#define I_  512
#define H_  1024
#define N3  3072                    // 3 * H (xc | xa | xh concatenated)
#define M_  (T_ * B_)               // 131072 rows of the projection GEMM

// Scratch for the fused input projections: [M_, 3072] fp32 (~1.6 GB).
__device__ float g_xall[(size_t)M_ * N3];

// ---------------------------------------------------------------------------
// Projection GEMM: C[m, n] = sum_k A[m,k] * Ucat[n,k] + bias[n]
// Ucat rows 0..1023 = U_c (+b_c), 1024..2047 = U_a (+b_a), 2048..3071 = U_h.
// 128x128 block tile, K-tile 8, 256 threads, 8x8 micro-tile per thread.
// ---------------------------------------------------------------------------
__global__ __launch_bounds__(256) void proj_kernel(
    const float* __restrict__ A,
    const float* __restrict__ Uc, const float* __restrict__ Ua,
    const float* __restrict__ Uh,
    const float* __restrict__ bc, const float* __restrict__ ba)
{
    __shared__ float As[8][128];
    __shared__ float Bs[8][128];

    const int tid = threadIdx.x;
    const int m0  = blockIdx.y * 128;
    const int n0  = blockIdx.x * 128;
    const int sel = n0 >> 10;                       // 0: U_c, 1: U_a, 2: U_h
    const float* __restrict__ U = (sel == 0) ? Uc : (sel == 1) ? Ua : Uh;
    const int noff = n0 & (H_ - 1);

    const int lrow = tid >> 1;                      // 0..127
    const int lk4  = (tid & 1) * 4;                 // 0 or 4

    const float* Aptr = A + (size_t)(m0 + lrow) * I_ + lk4;
    const float* Uptr = U + (size_t)(noff + lrow) * I_ + lk4;

    const int tx = tid & 15;                        // 0..15 (n direction)
    const int ty = tid >> 4;                        // 0..15 (m direction)

    float acc[8][8];
    #pragma unroll
    for (int i = 0; i < 8; i++)
        #pragma unroll
        for (int j = 0; j < 8; j++) acc[i][j] = 0.0f;

    for (int k0 = 0; k0 < I_; k0 += 8) {
        float4 av = *(const float4*)(Aptr + k0);
        float4 uv = *(const float4*)(Uptr + k0);
        __syncthreads();                            // prev compute done
        As[lk4 + 0][lrow] = av.x; As[lk4 + 1][lrow] = av.y;
        As[lk4 + 2][lrow] = av.z; As[lk4 + 3][lrow] = av.w;
        Bs[lk4 + 0][lrow] = uv.x; Bs[lk4 + 1][lrow] = uv.y;
        Bs[lk4 + 2][lrow] = uv.z; Bs[lk4 + 3][lrow] = uv.w;
        __syncthreads();

        #pragma unroll
        for (int k = 0; k < 8; k++) {
            float4 a0 = *(const float4*)&As[k][ty * 4];
            float4 a1 = *(const float4*)&As[k][64 + ty * 4];
            float4 b0 = *(const float4*)&Bs[k][tx * 4];
            float4 b1 = *(const float4*)&Bs[k][64 + tx * 4];
            float a[8] = {a0.x, a0.y, a0.z, a0.w, a1.x, a1.y, a1.z, a1.w};
            float b[8] = {b0.x, b0.y, b0.z, b0.w, b1.x, b1.y, b1.z, b1.w};
            #pragma unroll
            for (int i = 0; i < 8; i++)
                #pragma unroll
                for (int j = 0; j < 8; j++) acc[i][j] += a[i] * b[j];
        }
    }

    // Epilogue: add bias, vectorized stores.
    #pragma unroll
    for (int ii = 0; ii < 2; ii++) {
        #pragma unroll
        for (int i = 0; i < 4; i++) {
            int r = ii * 64 + ty * 4 + i;
            float* crow = &g_xall[(size_t)(m0 + r) * N3 + n0];
            #pragma unroll
            for (int jj = 0; jj < 2; jj++) {
                int cb = jj * 64 + tx * 4;
                float4 bv;
                if (sel == 0)      bv = *(const float4*)&bc[noff + cb];
                else if (sel == 1) bv = *(const float4*)&ba[noff + cb];
                else               bv = make_float4(0.f, 0.f, 0.f, 0.f);
                int ai = ii * 4 + i;
                float4 o;
                o.x = acc[ai][jj * 4 + 0] + bv.x;
                o.y = acc[ai][jj * 4 + 1] + bv.y;
                o.z = acc[ai][jj * 4 + 2] + bv.z;
                o.w = acc[ai][jj * 4 + 3] + bv.w;
                *(float4*)&crow[cb] = o;
            }
        }
    }
}

// ---------------------------------------------------------------------------
// One recurrence step:
//   c  = sigmoid(xc_t + h W_c^T)
//   a  = 1 + tanh(xa_t + h W_a^T)
//   h' = c*h + (1-c)*tanh(xh_t + a*h)
// Tile: 32 (b) x 64 (h), K-tile 16, 256 threads, 2x4 micro-tile, both W mats.
// Grid = 8 x 16 = 128 blocks.
// ---------------------------------------------------------------------------
__device__ __forceinline__ float nbrc_el(float cpre, float apre, float xh, float hp)
{
    float c = 1.0f / (1.0f + expf(-cpre));
    float a = 1.0f + tanhf(apre);
    return c * hp + (1.0f - c) * tanhf(xh + a * hp);
}

__global__ __launch_bounds__(256) void step_kernel(
    const float* __restrict__ hprev,    // [B_, H_]
    const float* __restrict__ Wc,       // [H_, H_]
    const float* __restrict__ Wa,       // [H_, H_]
    const float* __restrict__ xall_t,   // [B_, N3] for this timestep
    float* __restrict__ hout)           // [B_, H_]
{
    __shared__ float hs[16][34];        // [k][b], padded
    __shared__ float wcs[16][68];       // [k][h], padded
    __shared__ float was[16][68];

    const int tid = threadIdx.x;
    const int h0  = blockIdx.x * 64;
    const int b0  = blockIdx.y * 32;
    const int tx  = tid & 15;           // h direction (x4)
    const int ty  = tid >> 4;           // b direction (x2)

    const int lb  = tid >> 3;           // 0..31
    const int lk2 = (tid & 7) * 2;      // 0..14
    const int lh  = tid >> 2;           // 0..63
    const int lk4 = (tid & 3) * 4;      // 0..12

    const float* hptr  = hprev + (size_t)(b0 + lb) * H_ + lk2;
    const float* wcptr = Wc + (size_t)(h0 + lh) * H_ + lk4;
    const float* waptr = Wa + (size_t)(h0 + lh) * H_ + lk4;

    float accc[2][4], acca[2][4];
    #pragma unroll
    for (int i = 0; i < 2; i++)
        #pragma unroll
        for (int j = 0; j < 4; j++) { accc[i][j] = 0.f; acca[i][j] = 0.f; }

    for (int k0 = 0; k0 < H_; k0 += 16) {
        float2 hv = *(const float2*)(hptr + k0);
        float4 cv = *(const float4*)(wcptr + k0);
        float4 av = *(const float4*)(waptr + k0);
        __syncthreads();
        hs[lk2 + 0][lb] = hv.x; hs[lk2 + 1][lb] = hv.y;
        wcs[lk4 + 0][lh] = cv.x; wcs[lk4 + 1][lh] = cv.y;
        wcs[lk4 + 2][lh] = cv.z; wcs[lk4 + 3][lh] = cv.w;
        was[lk4 + 0][lh] = av.x; was[lk4 + 1][lh] = av.y;
        was[lk4 + 2][lh] = av.z; was[lk4 + 3][lh] = av.w;
        __syncthreads();

        #pragma unroll
        for (int k = 0; k < 16; k++) {
            float2 hr  = *(const float2*)&hs[k][ty * 2];
            float4 wc4 = *(const float4*)&wcs[k][tx * 4];
            float4 wa4 = *(const float4*)&was[k][tx * 4];
            accc[0][0] += hr.x * wc4.x; accc[0][1] += hr.x * wc4.y;
            accc[0][2] += hr.x * wc4.z; accc[0][3] += hr.x * wc4.w;
            accc[1][0] += hr.y * wc4.x; accc[1][1] += hr.y * wc4.y;
            accc[1][2] += hr.y * wc4.z; accc[1][3] += hr.y * wc4.w;
            acca[0][0] += hr.x * wa4.x; acca[0][1] += hr.x * wa4.y;
            acca[0][2] += hr.x * wa4.z; acca[0][3] += hr.x * wa4.w;
            acca[1][0] += hr.y * wa4.x; acca[1][1] += hr.y * wa4.y;
            acca[1][2] += hr.y * wa4.z; acca[1][3] += hr.y * wa4.w;
        }
    }

    const int hcol = h0 + tx * 4;
    #pragma unroll
    for (int ib = 0; ib < 2; ib++) {
        int b = b0 + ty * 2 + ib;
        const float* xrow = xall_t + (size_t)b * N3;
        float4 xc = *(const float4*)&xrow[hcol];
        float4 xa = *(const float4*)&xrow[1024 + hcol];
        float4 xh = *(const float4*)&xrow[2048 + hcol];
        float4 hp = *(const float4*)&hprev[(size_t)b * H_ + hcol];
        float4 o;
        o.x = nbrc_el(xc.x + accc[ib][0], xa.x + acca[ib][0], xh.x, hp.x);
        o.y = nbrc_el(xc.y + accc[ib][1], xa.y + acca[ib][1], xh.y, hp.y);
        o.z = nbrc_el(xc.z + accc[ib][2], xa.z + acca[ib][2], xh.z, hp.z);
        o.w = nbrc_el(xc.w + accc[ib][3], xa.w + acca[ib][3], xh.w, hp.w);
        *(float4*)&hout[(size_t)b * H_ + hcol] = o;
    }
}

// ---------------------------------------------------------------------------
// Launch: one big projection GEMM, then 512 sequential step kernels, each
// writing h_t straight into d_out[t] (which then serves as h_{t} input for
// step t+1). hn = copy of the last slice.
// ---------------------------------------------------------------------------
extern "C" void kernel_launch(void* const* d_in, const int* in_sizes, int n_in,
                              void* d_out, int out_size)
{
    const float* x   = (const float*)d_in[0];   // x_seq [T,B,I]
    const float* h0i = (const float*)d_in[1];   // h     [B,H]
    const float* Uc  = (const float*)d_in[2];   // [H,I]
    const float* Wc  = (const float*)d_in[3];   // [H,H]
    const float* bc  = (const float*)d_in[4];   // [H]
    const float* Ua  = (const float*)d_in[5];   // [H,I]
    const float* Wa  = (const float*)d_in[6];   // [H,H]
    const float* ba  = (const float*)d_in[7];   // [H]
    const float* Uh  = (const float*)d_in[8];   // [H,I]
    float* out = (float*)d_out;                 // [T,B,H] output then [B,H] hn

    float* xall = nullptr;
    cudaGetSymbolAddress((void**)&xall, g_xall);

    dim3 pgrid(N3 / 128, M_ / 128);
    proj_kernel<<<pgrid, 256>>>(x, Uc, Ua, Uh, bc, ba);

    dim3 sgrid(H_ / 64, B_ / 32);
    for (int t = 0; t < T_; t++) {
        const float* hp = (t == 0) ? h0i : out + (size_t)(t - 1) * B_ * H_;
        step_kernel<<<sgrid, 256>>>(hp, Wc, Wa,
                                    xall + (size_t)t * B_ * N3,
                                    out + (size_t)t * B_ * H_);
    }

    // hn = output[T-1]
    cudaMemcpyAsync(out + (size_t)T_ * B_ * H_,
                    out + (size_t)(T_ - 1) * B_ * H_,
                    (size_t)B_ * H_ * sizeof(float),
                    cudaMemcpyDeviceToDevice);
}

// round 8
// speedup vs baseline: 1.5545x; 1.5545x over previous
#include <cuda_runtime.h>
#include <cuda_bf16.h>
#include <math.h>
#include <stdint.h>

#define T_  512
#define B_  256
#define I_  512
#define H_  1024
#define N3  3072
#define M_  (T_ * B_)
#define NW  2048                     // rows of interleaved Wcat (c||a per 64-col block)

// tcgen05 is only legal on the sm_103a ("arch-accelerated") compile pass.
// The harness also builds a plain compute_103 pass; that pass gets a SIMT
// fallback body so ptxas succeeds. On GB300 the exact sm_103a cubin is loaded.
#if !defined(__CUDA_ARCH__) || defined(__CUDA_ARCH_FEAT_SM103_ALL) || defined(__CUDA_ARCH_FEAT_SM100_ALL) || defined(__CUDA_ARCH_FEAT_SM101_ALL)
#define TC_OK 1
#else
#define TC_OK 0
#endif

// ---------------- device scratch (no allocs allowed) -----------------------
__device__ float         g_xall[(size_t)M_ * N3];          // input projections
__device__ __nv_bfloat16 g_Whi[(size_t)NW * H_];
__device__ __nv_bfloat16 g_Wlo[(size_t)NW * H_];
__device__ __nv_bfloat16 g_hhi[2][(size_t)B_ * H_];        // double-buffered state
__device__ __nv_bfloat16 g_hlo[2][(size_t)B_ * H_];

// ---------------- PTX helpers ----------------------------------------------
__device__ __forceinline__ uint32_t smem_u32(const void* p) {
    uint32_t a;
    asm("{ .reg .u64 t; cvta.to.shared.u64 t, %1; cvt.u32.u64 %0, t; }" : "=r"(a) : "l"(p));
    return a;
}
__device__ __forceinline__ uint32_t elect1() {
    uint32_t p;
    asm volatile("{\n\t.reg .pred p;\n\telect.sync _|p, 0xFFFFFFFF;\n\tselp.b32 %0, 1, 0, p;\n\t}" : "=r"(p));
    return p;
}
__device__ __forceinline__ void mbar_init(uint32_t m, uint32_t cnt) {
    asm volatile("mbarrier.init.shared.b64 [%0], %1;" :: "r"(m), "r"(cnt) : "memory");
}
__device__ __forceinline__ void mbar_inval(uint32_t m) {
    asm volatile("mbarrier.inval.shared.b64 [%0];" :: "r"(m) : "memory");
}
__device__ __forceinline__ void mbar_wait(uint32_t m, uint32_t parity) {
    asm volatile(
        "{\n\t.reg .pred P;\n"
        "W%=:\n\t"
        "mbarrier.try_wait.parity.acquire.cta.shared::cta.b64 P, [%0], %1, 0x989680;\n\t"
        "@P bra D%=;\n\t"
        "bra W%=;\n"
        "D%=:\n\t}"
        :: "r"(m), "r"(parity) : "memory");
}
__device__ __forceinline__ void fence_async_shared() {
    asm volatile("fence.proxy.async.shared::cta;" ::: "memory");
}

#if TC_OK
__device__ __forceinline__ void tmem_alloc(uint32_t dst_smem, uint32_t ncols) {
    asm volatile("tcgen05.alloc.cta_group::1.sync.aligned.shared::cta.b32 [%0], %1;"
                 :: "r"(dst_smem), "r"(ncols) : "memory");
}
__device__ __forceinline__ void tmem_dealloc(uint32_t tmem, uint32_t ncols) {
    asm volatile("tcgen05.dealloc.cta_group::1.sync.aligned.b32 %0, %1;" :: "r"(tmem), "r"(ncols));
}
__device__ __forceinline__ void tmem_relinquish() {
    asm volatile("tcgen05.relinquish_alloc_permit.cta_group::1.sync.aligned;");
}
__device__ __forceinline__ void tc_commit(uint32_t m) {
    asm volatile("tcgen05.commit.cta_group::1.mbarrier::arrive::one.shared::cluster.b64 [%0];"
                 :: "r"(m) : "memory");
}
__device__ __forceinline__ void tc_fence_after() {
    asm volatile("tcgen05.fence::after_thread_sync;" ::: "memory");
}
__device__ __forceinline__ void tc_fence_before() {
    asm volatile("tcgen05.fence::before_thread_sync;" ::: "memory");
}
__device__ __forceinline__ void tc_wait_ld() {
    asm volatile("tcgen05.wait::ld.sync.aligned;" ::: "memory");
}
__device__ __forceinline__ void mma_f16_ss(uint32_t d, uint64_t ad, uint64_t bd,
                                           uint32_t idesc, uint32_t en) {
    asm volatile(
        "{\n\t.reg .pred p;\n\t"
        "setp.ne.u32 p, %4, 0;\n\t"
        "tcgen05.mma.cta_group::1.kind::f16 [%0], %1, %2, %3, {%5, %5, %5, %5}, p;\n\t}"
        :: "r"(d), "l"(ad), "l"(bd), "r"(idesc), "r"(en), "r"(0u) : "memory");
}
__device__ __forceinline__ void tmem_ld32(uint32_t* r, uint32_t addr) {
    asm volatile(
        "tcgen05.ld.sync.aligned.32x32b.x32.b32 "
        "{%0, %1, %2, %3, %4, %5, %6, %7, "
        " %8, %9, %10, %11, %12, %13, %14, %15, "
        " %16, %17, %18, %19, %20, %21, %22, %23, "
        " %24, %25, %26, %27, %28, %29, %30, %31}, [%32];"
        : "=r"(r[0]), "=r"(r[1]), "=r"(r[2]), "=r"(r[3]),
          "=r"(r[4]), "=r"(r[5]), "=r"(r[6]), "=r"(r[7]),
          "=r"(r[8]), "=r"(r[9]), "=r"(r[10]), "=r"(r[11]),
          "=r"(r[12]), "=r"(r[13]), "=r"(r[14]), "=r"(r[15]),
          "=r"(r[16]), "=r"(r[17]), "=r"(r[18]), "=r"(r[19]),
          "=r"(r[20]), "=r"(r[21]), "=r"(r[22]), "=r"(r[23]),
          "=r"(r[24]), "=r"(r[25]), "=r"(r[26]), "=r"(r[27]),
          "=r"(r[28]), "=r"(r[29]), "=r"(r[30]), "=r"(r[31])
        : "r"(addr));
}
#endif  // TC_OK

#define SWZ(o) ((o) ^ (((o) >> 3) & 0x70))
static __device__ __forceinline__ uint64_t smem_desc(uint32_t addr) {
    const uint64_t base = (2ull << 61) | (1ull << 46) | (64ull << 32) | (1ull << 16);
    return base | ((addr >> 4) & 0x3FFF);
}
// idesc: kind::f16, dtype=F32, a=b=BF16, N=128, M=128
#define IDESC 0x8200490u

// ---------------------------------------------------------------------------
// Projection GEMM: g_xall[m, 3072] = x @ Ucat^T + b   (~1 ms)
// ---------------------------------------------------------------------------
__global__ __launch_bounds__(256) void proj_kernel(
    const float* __restrict__ A,
    const float* __restrict__ Uc, const float* __restrict__ Ua,
    const float* __restrict__ Uh,
    const float* __restrict__ bc, const float* __restrict__ ba)
{
    __shared__ float As[8][128];
    __shared__ float Bs[8][128];

    const int tid = threadIdx.x;
    const int m0  = blockIdx.y * 128;
    const int n0  = blockIdx.x * 128;
    const int sel = n0 >> 10;
    const float* __restrict__ U = (sel == 0) ? Uc : (sel == 1) ? Ua : Uh;
    const int noff = n0 & (H_ - 1);

    const int lrow = tid >> 1;
    const int lk4  = (tid & 1) * 4;

    const float* Aptr = A + (size_t)(m0 + lrow) * I_ + lk4;
    const float* Uptr = U + (size_t)(noff + lrow) * I_ + lk4;

    const int tx = tid & 15;
    const int ty = tid >> 4;

    float acc[8][8];
    #pragma unroll
    for (int i = 0; i < 8; i++)
        #pragma unroll
        for (int j = 0; j < 8; j++) acc[i][j] = 0.0f;

    for (int k0 = 0; k0 < I_; k0 += 8) {
        float4 av = *(const float4*)(Aptr + k0);
        float4 uv = *(const float4*)(Uptr + k0);
        __syncthreads();
        As[lk4 + 0][lrow] = av.x; As[lk4 + 1][lrow] = av.y;
        As[lk4 + 2][lrow] = av.z; As[lk4 + 3][lrow] = av.w;
        Bs[lk4 + 0][lrow] = uv.x; Bs[lk4 + 1][lrow] = uv.y;
        Bs[lk4 + 2][lrow] = uv.z; Bs[lk4 + 3][lrow] = uv.w;
        __syncthreads();

        #pragma unroll
        for (int k = 0; k < 8; k++) {
            float4 a0 = *(const float4*)&As[k][ty * 4];
            float4 a1 = *(const float4*)&As[k][64 + ty * 4];
            float4 b0 = *(const float4*)&Bs[k][tx * 4];
            float4 b1 = *(const float4*)&Bs[k][64 + tx * 4];
            float a[8] = {a0.x, a0.y, a0.z, a0.w, a1.x, a1.y, a1.z, a1.w};
            float b[8] = {b0.x, b0.y, b0.z, b0.w, b1.x, b1.y, b1.z, b1.w};
            #pragma unroll
            for (int i = 0; i < 8; i++)
                #pragma unroll
                for (int j = 0; j < 8; j++) acc[i][j] += a[i] * b[j];
        }
    }

    #pragma unroll
    for (int ii = 0; ii < 2; ii++) {
        #pragma unroll
        for (int i = 0; i < 4; i++) {
            int r = ii * 64 + ty * 4 + i;
            float* crow = &g_xall[(size_t)(m0 + r) * N3 + n0];
            #pragma unroll
            for (int jj = 0; jj < 2; jj++) {
                int cb = jj * 64 + tx * 4;
                float4 bv;
                if (sel == 0)      bv = *(const float4*)&bc[noff + cb];
                else if (sel == 1) bv = *(const float4*)&ba[noff + cb];
                else               bv = make_float4(0.f, 0.f, 0.f, 0.f);
                int ai = ii * 4 + i;
                float4 o;
                o.x = acc[ai][jj * 4 + 0] + bv.x;
                o.y = acc[ai][jj * 4 + 1] + bv.y;
                o.z = acc[ai][jj * 4 + 2] + bv.z;
                o.w = acc[ai][jj * 4 + 3] + bv.w;
                *(float4*)&crow[cb] = o;
            }
        }
    }
}

// ---------------------------------------------------------------------------
// Pack W_c, W_a into interleaved bf16 hi/lo Wcat:
// row r: j=r>>7, m=(r>>6)&1, i=r&63  ->  W_m[64j+i]
// ---------------------------------------------------------------------------
__global__ __launch_bounds__(256) void pack_w(const float* __restrict__ Wc,
                                              const float* __restrict__ Wa)
{
    int idx = blockIdx.x * 256 + threadIdx.x;       // 0..524287 (x4 elems)
    int r  = idx >> 8;
    int c4 = (idx & 255) * 4;
    int j = r >> 7, m = (r >> 6) & 1, i = r & 63;
    const float* src = (m ? Wa : Wc) + (size_t)(64 * j + i) * H_ + c4;
    float4 v = *(const float4*)src;

    __nv_bfloat16 h0 = __float2bfloat16(v.x), h1 = __float2bfloat16(v.y);
    __nv_bfloat16 h2 = __float2bfloat16(v.z), h3 = __float2bfloat16(v.w);
    __nv_bfloat16 l0 = __float2bfloat16(v.x - __bfloat162float(h0));
    __nv_bfloat16 l1 = __float2bfloat16(v.y - __bfloat162float(h1));
    __nv_bfloat16 l2 = __float2bfloat16(v.z - __bfloat162float(h2));
    __nv_bfloat16 l3 = __float2bfloat16(v.w - __bfloat162float(h3));

    __nv_bfloat16* dh = g_Whi + (size_t)r * H_ + c4;
    __nv_bfloat16* dl = g_Wlo + (size_t)r * H_ + c4;
    __nv_bfloat162 p;
    p.x = h0; p.y = h1; *(__nv_bfloat162*)(dh + 0) = p;
    p.x = h2; p.y = h3; *(__nv_bfloat162*)(dh + 2) = p;
    p.x = l0; p.y = l1; *(__nv_bfloat162*)(dl + 0) = p;
    p.x = l2; p.y = l3; *(__nv_bfloat162*)(dl + 2) = p;
}

// h0 fp32 -> hi/lo bf16 into state buffer 0
__global__ __launch_bounds__(256) void conv_h0(const float* __restrict__ h)
{
    int idx = blockIdx.x * 256 + threadIdx.x;       // 65536, x4 elems
    float4 v = *(const float4*)(h + (size_t)idx * 4);
    __nv_bfloat16 h0 = __float2bfloat16(v.x), h1 = __float2bfloat16(v.y);
    __nv_bfloat16 h2 = __float2bfloat16(v.z), h3 = __float2bfloat16(v.w);
    __nv_bfloat16 l0 = __float2bfloat16(v.x - __bfloat162float(h0));
    __nv_bfloat16 l1 = __float2bfloat16(v.y - __bfloat162float(h1));
    __nv_bfloat16 l2 = __float2bfloat16(v.z - __bfloat162float(h2));
    __nv_bfloat16 l3 = __float2bfloat16(v.w - __bfloat162float(h3));
    __nv_bfloat16* dh = g_hhi[0] + (size_t)idx * 4;
    __nv_bfloat16* dl = g_hlo[0] + (size_t)idx * 4;
    __nv_bfloat162 p;
    p.x = h0; p.y = h1; *(__nv_bfloat162*)(dh + 0) = p;
    p.x = h2; p.y = h3; *(__nv_bfloat162*)(dh + 2) = p;
    p.x = l0; p.y = l1; *(__nv_bfloat162*)(dl + 0) = p;
    p.x = l2; p.y = l3; *(__nv_bfloat162*)(dl + 2) = p;
}

// ---------------------------------------------------------------------------
// One recurrence step on tensor cores (sm_103a pass) / SIMT fallback (plain).
// CTA tile: M=128 (batch), N=128 (= 64 h-cols x {c,a}); K=1024 in 16 chunks
// of 64 bf16 (128B SW128 rows). 3 MMA products per sub-k: hi*hi, hi*lo, lo*hi.
// Grid (16, 2) = 32 CTAs, 256 threads. Double-buffered smem, mbarrier-tracked.
// ---------------------------------------------------------------------------
#define KC       64
#define TILE_B   16384                 // 128 rows * 128B
#define BUF_B    (4 * TILE_B)          // Ahi|Alo|Bhi|Blo
#define DYN_SMEM (2 * BUF_B + 1024)    // +1KB so we can align base to 1024B

__device__ __forceinline__ float nbrc_el(float cpre, float apre, float xh, float hp)
{
    float c = 1.0f / (1.0f + expf(-cpre));
    float a = 1.0f + tanhf(apre);
    return c * hp + (1.0f - c) * tanhf(xh + a * hp);
}

__device__ __forceinline__ void store_hilo(__nv_bfloat16* dh, __nv_bfloat16* dl, float4 o)
{
    __nv_bfloat16 h0 = __float2bfloat16(o.x), h1 = __float2bfloat16(o.y);
    __nv_bfloat16 h2 = __float2bfloat16(o.z), h3 = __float2bfloat16(o.w);
    __nv_bfloat16 l0 = __float2bfloat16(o.x - __bfloat162float(h0));
    __nv_bfloat16 l1 = __float2bfloat16(o.y - __bfloat162float(h1));
    __nv_bfloat16 l2 = __float2bfloat16(o.z - __bfloat162float(h2));
    __nv_bfloat16 l3 = __float2bfloat16(o.w - __bfloat162float(h3));
    __nv_bfloat162 p;
    p.x = h0; p.y = h1; *(__nv_bfloat162*)(dh + 0) = p;
    p.x = h2; p.y = h3; *(__nv_bfloat162*)(dh + 2) = p;
    p.x = l0; p.y = l1; *(__nv_bfloat162*)(dl + 0) = p;
    p.x = l2; p.y = l3; *(__nv_bfloat162*)(dl + 2) = p;
}

__global__ __launch_bounds__(256, 1) void step_mma(
    int t, int sbuf,
    const float* __restrict__ hprev,    // fp32 [B_,H_] (out[t-1] or input h)
    float* __restrict__ hout)           // fp32 out[t]
{
#if TC_OK
    extern __shared__ char dynraw[];
    __shared__ uint32_t s_tmem[1];
    __shared__ __align__(8) uint64_t s_mbar[2];

    const int tid = threadIdx.x;
    const int wid = tid >> 5;
    const int m0  = blockIdx.y * 128;           // batch tile
    const int n0  = blockIdx.x * 128;           // Wcat row tile
    const int jh  = blockIdx.x * 64;            // h-column base

    // SW128 swizzle is computed by HW from ABSOLUTE smem address bits [9:7];
    // the tile base MUST be 1024-byte aligned. Static __shared__ above shifts
    // the dynamic segment, so align manually (R7 bug fix).
    const uint32_t rawb = smem_u32(dynraw);
    const uint32_t dynb = (rawb + 1023u) & ~1023u;
    char* dyn = dynraw + (dynb - rawb);

    const __nv_bfloat16* __restrict__ hhi = g_hhi[sbuf];
    const __nv_bfloat16* __restrict__ hlo = g_hlo[sbuf];
    __nv_bfloat16* __restrict__ nhhi = g_hhi[sbuf ^ 1];
    __nv_bfloat16* __restrict__ nhlo = g_hlo[sbuf ^ 1];

    const uint32_t mb[2] = { smem_u32(&s_mbar[0]), smem_u32(&s_mbar[1]) };

    if (wid == 0) tmem_alloc(smem_u32(s_tmem), 128);
    if (tid == 0) { mbar_init(mb[0], 1); mbar_init(mb[1], 1); }
    __syncthreads();
    const uint32_t tmem = s_tmem[0];

    // per-thread load geometry: 4 iters, row = r0 + 32i, unit = tid&7 (16B)
    const int r0 = tid >> 3;
    const int un = tid & 7;
    uint32_t swz[4];
    #pragma unroll
    for (int i = 0; i < 4; i++) {
        uint32_t o = (uint32_t)(r0 + 32 * i) * 128u + (uint32_t)un * 16u;
        swz[i] = SWZ(o);
    }

    // ---- preload chunk 0 ----
    {
        #pragma unroll
        for (int i = 0; i < 4; i++) {
            int row = r0 + 32 * i;
            size_t aofs = (size_t)(m0 + row) * H_ + un * 8;
            size_t bofs = (size_t)(n0 + row) * H_ + un * 8;
            uint4 va = *(const uint4*)(hhi   + aofs);
            uint4 vb = *(const uint4*)(hlo   + aofs);
            uint4 vc = *(const uint4*)(g_Whi + bofs);
            uint4 vd = *(const uint4*)(g_Wlo + bofs);
            *(uint4*)(dyn + 0 * TILE_B + swz[i]) = va;
            *(uint4*)(dyn + 1 * TILE_B + swz[i]) = vb;
            *(uint4*)(dyn + 2 * TILE_B + swz[i]) = vc;
            *(uint4*)(dyn + 3 * TILE_B + swz[i]) = vd;
        }
    }
    fence_async_shared();
    __syncthreads();

    int ph0 = 0, ph1 = 0;
    #pragma unroll 1
    for (int c = 0; c < 16; c++) {
        const int cur = c & 1;

        // issue LDG for next chunk (overlaps with MMA below)
        uint4 ra[4], rb[4], rc[4], rd[4];
        if (c < 15) {
            const int k0 = (c + 1) * KC;
            #pragma unroll
            for (int i = 0; i < 4; i++) {
                int row = r0 + 32 * i;
                size_t aofs = (size_t)(m0 + row) * H_ + k0 + un * 8;
                size_t bofs = (size_t)(n0 + row) * H_ + k0 + un * 8;
                ra[i] = *(const uint4*)(hhi   + aofs);
                rb[i] = *(const uint4*)(hlo   + aofs);
                rc[i] = *(const uint4*)(g_Whi + bofs);
                rd[i] = *(const uint4*)(g_Wlo + bofs);
            }
        }

        // MMA on current buffer
        if (wid == 0 && elect1()) {
            uint32_t ab = dynb + cur * BUF_B;
            uint64_t dah = smem_desc(ab + 0 * TILE_B);
            uint64_t dal = smem_desc(ab + 1 * TILE_B);
            uint64_t dbh = smem_desc(ab + 2 * TILE_B);
            uint64_t dbl = smem_desc(ab + 3 * TILE_B);
            #pragma unroll
            for (int s = 0; s < 4; s++) {        // 4 x K=16 within the chunk
                mma_f16_ss(tmem, dah + 2 * s, dbh + 2 * s, IDESC, (c | s) != 0);
                mma_f16_ss(tmem, dah + 2 * s, dbl + 2 * s, IDESC, 1);
                mma_f16_ss(tmem, dal + 2 * s, dbh + 2 * s, IDESC, 1);
            }
            tc_commit(mb[cur]);
        }

        if (c < 15) {
            const int nxt = 1 - cur;
            if (c >= 1) {                        // chunk c-1's MMA on buf nxt
                if (nxt == 0) { mbar_wait(mb[0], ph0); ph0 ^= 1; }
                else          { mbar_wait(mb[1], ph1); ph1 ^= 1; }
            }
            char* bb = dyn + nxt * BUF_B;
            #pragma unroll
            for (int i = 0; i < 4; i++) {
                *(uint4*)(bb + 0 * TILE_B + swz[i]) = ra[i];
                *(uint4*)(bb + 1 * TILE_B + swz[i]) = rb[i];
                *(uint4*)(bb + 2 * TILE_B + swz[i]) = rc[i];
                *(uint4*)(bb + 3 * TILE_B + swz[i]) = rd[i];
            }
            fence_async_shared();
            __syncthreads();
        }
    }

    // drain remaining MMA completions
    mbar_wait(mb[0], ph0);
    mbar_wait(mb[1], ph1);
    tc_fence_after();

    // ---- epilogue: 8 warps; warp w -> rows of subpartition (w&3), cols half (w>>2)
    {
        const int lane = tid & 31;
        const int sub  = wid & 3;
        const int half = wid >> 2;
        const int b    = m0 + sub * 32 + lane;

        uint32_t dc[32], da[32];
        tmem_ld32(dc, tmem + half * 32);          // c-preact cols
        tmem_ld32(da, tmem + 64 + half * 32);     // a-preact cols
        tc_wait_ld();
        tc_fence_before();

        const float* xrow = g_xall + (size_t)t * B_ * N3 + (size_t)b * N3;
        const int hb = jh + half * 32;

        #pragma unroll
        for (int i = 0; i < 32; i += 4) {
            int hc = hb + i;
            float4 xc = *(const float4*)(xrow + hc);
            float4 xa = *(const float4*)(xrow + 1024 + hc);
            float4 xh = *(const float4*)(xrow + 2048 + hc);
            float4 hp = *(const float4*)(hprev + (size_t)b * H_ + hc);
            float4 o;
            o.x = nbrc_el(xc.x + __uint_as_float(dc[i + 0]), xa.x + __uint_as_float(da[i + 0]), xh.x, hp.x);
            o.y = nbrc_el(xc.y + __uint_as_float(dc[i + 1]), xa.y + __uint_as_float(da[i + 1]), xh.y, hp.y);
            o.z = nbrc_el(xc.z + __uint_as_float(dc[i + 2]), xa.z + __uint_as_float(da[i + 2]), xh.z, hp.z);
            o.w = nbrc_el(xc.w + __uint_as_float(dc[i + 3]), xa.w + __uint_as_float(da[i + 3]), xh.w, hp.w);
            *(float4*)(hout + (size_t)b * H_ + hc) = o;
            store_hilo(nhhi + (size_t)b * H_ + hc, nhlo + (size_t)b * H_ + hc, o);
        }
    }

    __syncthreads();
    if (tid == 0) { mbar_inval(mb[0]); mbar_inval(mb[1]); }
    __syncthreads();
    if (wid == 0) {
        tmem_relinquish();
        tmem_dealloc(tmem, 128);
    }
#else
    // ---- SIMT fallback (plain compute_103 pass; never selected on GB300) ----
    const int tid = threadIdx.x;
    const int m0  = blockIdx.y * 128;
    const int n0  = blockIdx.x * 128;
    const int jh  = blockIdx.x * 64;
    const int sbx = sbuf ^ 1;

    const int b    = m0 + (tid >> 1);          // 128 batch rows / CTA
    const int half = tid & 1;                  // 32-col half

    const float* xrow = g_xall + (size_t)t * B_ * N3 + (size_t)b * N3;
    for (int j = 0; j < 32; j++) {
        const int hc   = jh + half * 32 + j;
        const int rowc = n0 + half * 32 + j;
        const int rowa = rowc + 64;
        float sc = 0.f, sa = 0.f;
        const float* hp = hprev + (size_t)b * H_;
        for (int k = 0; k < H_; k++) {
            float wc = __bfloat162float(g_Whi[(size_t)rowc * H_ + k]) +
                       __bfloat162float(g_Wlo[(size_t)rowc * H_ + k]);
            float wa = __bfloat162float(g_Whi[(size_t)rowa * H_ + k]) +
                       __bfloat162float(g_Wlo[(size_t)rowa * H_ + k]);
            sc += hp[k] * wc;
            sa += hp[k] * wa;
        }
        float hpv = hprev[(size_t)b * H_ + hc];
        float o = nbrc_el(xrow[hc] + sc, xrow[1024 + hc] + sa, xrow[2048 + hc], hpv);
        hout[(size_t)b * H_ + hc] = o;
        __nv_bfloat16 hi = __float2bfloat16(o);
        __nv_bfloat16 lo = __float2bfloat16(o - __bfloat162float(hi));
        g_hhi[sbx][(size_t)b * H_ + hc] = hi;
        g_hlo[sbx][(size_t)b * H_ + hc] = lo;
    }
#endif
}

// ---------------------------------------------------------------------------
extern "C" void kernel_launch(void* const* d_in, const int* in_sizes, int n_in,
                              void* d_out, int out_size)
{
    const float* x   = (const float*)d_in[0];
    const float* h0i = (const float*)d_in[1];
    const float* Uc  = (const float*)d_in[2];
    const float* Wc  = (const float*)d_in[3];
    const float* bc  = (const float*)d_in[4];
    const float* Ua  = (const float*)d_in[5];
    const float* Wa  = (const float*)d_in[6];
    const float* ba  = (const float*)d_in[7];
    const float* Uh  = (const float*)d_in[8];
    float* out = (float*)d_out;

    cudaFuncSetAttribute(step_mma, cudaFuncAttributeMaxDynamicSharedMemorySize, DYN_SMEM);

    pack_w<<<2048, 256>>>(Wc, Wa);
    conv_h0<<<256, 256>>>(h0i);

    dim3 pgrid(N3 / 128, M_ / 128);
    proj_kernel<<<pgrid, 256>>>(x, Uc, Ua, Uh, bc, ba);

    dim3 sgrid(16, 2);
    for (int t = 0; t < T_; t++) {
        const float* hp = (t == 0) ? h0i : out + (size_t)(t - 1) * B_ * H_;
        step_mma<<<sgrid, 256, DYN_SMEM>>>(t, t & 1, hp, out + (size_t)t * B_ * H_);
    }

    cudaMemcpyAsync(out + (size_t)T_ * B_ * H_,
                    out + (size_t)(T_ - 1) * B_ * H_,
                    (size_t)B_ * H_ * sizeof(float),
                    cudaMemcpyDeviceToDevice);
}

// round 9
// speedup vs baseline: 2.2070x; 1.4198x over previous
#include <cuda_runtime.h>
#include <cuda_bf16.h>
#include <math.h>
#include <stdint.h>

#define T_  512
#define B_  256
#define I_  512
#define H_  1024
#define N3  3072
#define M_  (T_ * B_)
#define NW  2048                     // rows of interleaved Wcat (c||a per 32-col block)

#if !defined(__CUDA_ARCH__) || defined(__CUDA_ARCH_FEAT_SM103_ALL) || defined(__CUDA_ARCH_FEAT_SM100_ALL) || defined(__CUDA_ARCH_FEAT_SM101_ALL)
#define TC_OK 1
#else
#define TC_OK 0
#endif

// ---------------- device scratch -----------------------
__device__ float         g_xall[(size_t)M_ * N3];
__device__ __nv_bfloat16 g_Whi[(size_t)NW * H_];
__device__ __nv_bfloat16 g_Wlo[(size_t)NW * H_];
__device__ __nv_bfloat16 g_hhi[2][(size_t)B_ * H_];
__device__ __nv_bfloat16 g_hlo[2][(size_t)B_ * H_];

// ---------------- PTX helpers ----------------------------------------------
__device__ __forceinline__ uint32_t smem_u32(const void* p) {
    uint32_t a;
    asm("{ .reg .u64 t; cvta.to.shared.u64 t, %1; cvt.u32.u64 %0, t; }" : "=r"(a) : "l"(p));
    return a;
}
__device__ __forceinline__ uint32_t elect1() {
    uint32_t p;
    asm volatile("{\n\t.reg .pred p;\n\telect.sync _|p, 0xFFFFFFFF;\n\tselp.b32 %0, 1, 0, p;\n\t}" : "=r"(p));
    return p;
}
__device__ __forceinline__ void mbar_init(uint32_t m, uint32_t cnt) {
    asm volatile("mbarrier.init.shared.b64 [%0], %1;" :: "r"(m), "r"(cnt) : "memory");
}
__device__ __forceinline__ void mbar_inval(uint32_t m) {
    asm volatile("mbarrier.inval.shared.b64 [%0];" :: "r"(m) : "memory");
}
__device__ __forceinline__ void mbar_wait(uint32_t m, uint32_t parity) {
    asm volatile(
        "{\n\t.reg .pred P;\n"
        "W%=:\n\t"
        "mbarrier.try_wait.parity.acquire.cta.shared::cta.b64 P, [%0], %1, 0x989680;\n\t"
        "@P bra D%=;\n\t"
        "bra W%=;\n"
        "D%=:\n\t}"
        :: "r"(m), "r"(parity) : "memory");
}
__device__ __forceinline__ void fence_async_shared() {
    asm volatile("fence.proxy.async.shared::cta;" ::: "memory");
}
__device__ __forceinline__ void cp16(uint32_t dst, const void* src) {
    asm volatile("cp.async.cg.shared.global [%0], [%1], 16;" :: "r"(dst), "l"(src) : "memory");
}
#define CP_COMMIT() asm volatile("cp.async.commit_group;" ::: "memory")
#define CP_WAIT2()  asm volatile("cp.async.wait_group 2;" ::: "memory")

#if TC_OK
__device__ __forceinline__ void tmem_alloc(uint32_t dst_smem, uint32_t ncols) {
    asm volatile("tcgen05.alloc.cta_group::1.sync.aligned.shared::cta.b32 [%0], %1;"
                 :: "r"(dst_smem), "r"(ncols) : "memory");
}
__device__ __forceinline__ void tmem_dealloc(uint32_t tmem, uint32_t ncols) {
    asm volatile("tcgen05.dealloc.cta_group::1.sync.aligned.b32 %0, %1;" :: "r"(tmem), "r"(ncols));
}
__device__ __forceinline__ void tmem_relinquish() {
    asm volatile("tcgen05.relinquish_alloc_permit.cta_group::1.sync.aligned;");
}
__device__ __forceinline__ void tc_commit(uint32_t m) {
    asm volatile("tcgen05.commit.cta_group::1.mbarrier::arrive::one.shared::cluster.b64 [%0];"
                 :: "r"(m) : "memory");
}
__device__ __forceinline__ void tc_fence_after() {
    asm volatile("tcgen05.fence::after_thread_sync;" ::: "memory");
}
__device__ __forceinline__ void tc_fence_before() {
    asm volatile("tcgen05.fence::before_thread_sync;" ::: "memory");
}
__device__ __forceinline__ void tc_wait_ld() {
    asm volatile("tcgen05.wait::ld.sync.aligned;" ::: "memory");
}
__device__ __forceinline__ void mma_f16_ss(uint32_t d, uint64_t ad, uint64_t bd,
                                           uint32_t idesc, uint32_t en) {
    asm volatile(
        "{\n\t.reg .pred p;\n\t"
        "setp.ne.u32 p, %4, 0;\n\t"
        "tcgen05.mma.cta_group::1.kind::f16 [%0], %1, %2, %3, {%5, %5, %5, %5}, p;\n\t}"
        :: "r"(d), "l"(ad), "l"(bd), "r"(idesc), "r"(en), "r"(0u) : "memory");
}
__device__ __forceinline__ void tmem_ld16(uint32_t* r, uint32_t addr) {
    asm volatile(
        "tcgen05.ld.sync.aligned.32x32b.x16.b32 "
        "{%0, %1, %2, %3, %4, %5, %6, %7, "
        " %8, %9, %10, %11, %12, %13, %14, %15}, [%16];"
        : "=r"(r[0]), "=r"(r[1]), "=r"(r[2]), "=r"(r[3]),
          "=r"(r[4]), "=r"(r[5]), "=r"(r[6]), "=r"(r[7]),
          "=r"(r[8]), "=r"(r[9]), "=r"(r[10]), "=r"(r[11]),
          "=r"(r[12]), "=r"(r[13]), "=r"(r[14]), "=r"(r[15])
        : "r"(addr));
}
#endif  // TC_OK

#define SWZ(o) ((o) ^ (((o) >> 3) & 0x70))
static __device__ __forceinline__ uint64_t smem_desc(uint32_t addr) {
    const uint64_t base = (2ull << 61) | (1ull << 46) | (64ull << 32) | (1ull << 16);
    return base | ((addr >> 4) & 0x3FFF);
}
// idesc: kind::f16, dtype=F32, a=b=BF16, M=128, N=64
#define IDESC64 0x8100490u

// ---------------------------------------------------------------------------
// Projection GEMM: g_xall[m, 3072] = x @ Ucat^T + b   (~1 ms)
// ---------------------------------------------------------------------------
__global__ __launch_bounds__(256) void proj_kernel(
    const float* __restrict__ A,
    const float* __restrict__ Uc, const float* __restrict__ Ua,
    const float* __restrict__ Uh,
    const float* __restrict__ bc, const float* __restrict__ ba)
{
    __shared__ float As[8][128];
    __shared__ float Bs[8][128];

    const int tid = threadIdx.x;
    const int m0  = blockIdx.y * 128;
    const int n0  = blockIdx.x * 128;
    const int sel = n0 >> 10;
    const float* __restrict__ U = (sel == 0) ? Uc : (sel == 1) ? Ua : Uh;
    const int noff = n0 & (H_ - 1);

    const int lrow = tid >> 1;
    const int lk4  = (tid & 1) * 4;

    const float* Aptr = A + (size_t)(m0 + lrow) * I_ + lk4;
    const float* Uptr = U + (size_t)(noff + lrow) * I_ + lk4;

    const int tx = tid & 15;
    const int ty = tid >> 4;

    float acc[8][8];
    #pragma unroll
    for (int i = 0; i < 8; i++)
        #pragma unroll
        for (int j = 0; j < 8; j++) acc[i][j] = 0.0f;

    for (int k0 = 0; k0 < I_; k0 += 8) {
        float4 av = *(const float4*)(Aptr + k0);
        float4 uv = *(const float4*)(Uptr + k0);
        __syncthreads();
        As[lk4 + 0][lrow] = av.x; As[lk4 + 1][lrow] = av.y;
        As[lk4 + 2][lrow] = av.z; As[lk4 + 3][lrow] = av.w;
        Bs[lk4 + 0][lrow] = uv.x; Bs[lk4 + 1][lrow] = uv.y;
        Bs[lk4 + 2][lrow] = uv.z; Bs[lk4 + 3][lrow] = uv.w;
        __syncthreads();

        #pragma unroll
        for (int k = 0; k < 8; k++) {
            float4 a0 = *(const float4*)&As[k][ty * 4];
            float4 a1 = *(const float4*)&As[k][64 + ty * 4];
            float4 b0 = *(const float4*)&Bs[k][tx * 4];
            float4 b1 = *(const float4*)&Bs[k][64 + tx * 4];
            float a[8] = {a0.x, a0.y, a0.z, a0.w, a1.x, a1.y, a1.z, a1.w};
            float b[8] = {b0.x, b0.y, b0.z, b0.w, b1.x, b1.y, b1.z, b1.w};
            #pragma unroll
            for (int i = 0; i < 8; i++)
                #pragma unroll
                for (int j = 0; j < 8; j++) acc[i][j] += a[i] * b[j];
        }
    }

    #pragma unroll
    for (int ii = 0; ii < 2; ii++) {
        #pragma unroll
        for (int i = 0; i < 4; i++) {
            int r = ii * 64 + ty * 4 + i;
            float* crow = &g_xall[(size_t)(m0 + r) * N3 + n0];
            #pragma unroll
            for (int jj = 0; jj < 2; jj++) {
                int cb = jj * 64 + tx * 4;
                float4 bv;
                if (sel == 0)      bv = *(const float4*)&bc[noff + cb];
                else if (sel == 1) bv = *(const float4*)&ba[noff + cb];
                else               bv = make_float4(0.f, 0.f, 0.f, 0.f);
                int ai = ii * 4 + i;
                float4 o;
                o.x = acc[ai][jj * 4 + 0] + bv.x;
                o.y = acc[ai][jj * 4 + 1] + bv.y;
                o.z = acc[ai][jj * 4 + 2] + bv.z;
                o.w = acc[ai][jj * 4 + 3] + bv.w;
                *(float4*)&crow[cb] = o;
            }
        }
    }
}

// ---------------------------------------------------------------------------
// Pack W_c, W_a into interleaved bf16 hi/lo Wcat (32-column blocks for N=64
// tiles): row r: j=r>>6 (h-block of 32), m=(r>>5)&1, i=r&31 -> W_m[32j+i].
// ---------------------------------------------------------------------------
__global__ __launch_bounds__(256) void pack_w(const float* __restrict__ Wc,
                                              const float* __restrict__ Wa)
{
    int idx = blockIdx.x * 256 + threadIdx.x;       // 0..524287 (x4 elems)
    int r  = idx >> 8;
    int c4 = (idx & 255) * 4;
    int j = r >> 6, m = (r >> 5) & 1, i = r & 31;
    const float* src = (m ? Wa : Wc) + (size_t)(32 * j + i) * H_ + c4;
    float4 v = *(const float4*)src;

    __nv_bfloat16 h0 = __float2bfloat16(v.x), h1 = __float2bfloat16(v.y);
    __nv_bfloat16 h2 = __float2bfloat16(v.z), h3 = __float2bfloat16(v.w);
    __nv_bfloat16 l0 = __float2bfloat16(v.x - __bfloat162float(h0));
    __nv_bfloat16 l1 = __float2bfloat16(v.y - __bfloat162float(h1));
    __nv_bfloat16 l2 = __float2bfloat16(v.z - __bfloat162float(h2));
    __nv_bfloat16 l3 = __float2bfloat16(v.w - __bfloat162float(h3));

    __nv_bfloat16* dh = g_Whi + (size_t)r * H_ + c4;
    __nv_bfloat16* dl = g_Wlo + (size_t)r * H_ + c4;
    __nv_bfloat162 p;
    p.x = h0; p.y = h1; *(__nv_bfloat162*)(dh + 0) = p;
    p.x = h2; p.y = h3; *(__nv_bfloat162*)(dh + 2) = p;
    p.x = l0; p.y = l1; *(__nv_bfloat162*)(dl + 0) = p;
    p.x = l2; p.y = l3; *(__nv_bfloat162*)(dl + 2) = p;
}

// h0 fp32 -> hi/lo bf16 into state buffer 0
__global__ __launch_bounds__(256) void conv_h0(const float* __restrict__ h)
{
    int idx = blockIdx.x * 256 + threadIdx.x;       // 65536, x4 elems
    float4 v = *(const float4*)(h + (size_t)idx * 4);
    __nv_bfloat16 h0 = __float2bfloat16(v.x), h1 = __float2bfloat16(v.y);
    __nv_bfloat16 h2 = __float2bfloat16(v.z), h3 = __float2bfloat16(v.w);
    __nv_bfloat16 l0 = __float2bfloat16(v.x - __bfloat162float(h0));
    __nv_bfloat16 l1 = __float2bfloat16(v.y - __bfloat162float(h1));
    __nv_bfloat16 l2 = __float2bfloat16(v.z - __bfloat162float(h2));
    __nv_bfloat16 l3 = __float2bfloat16(v.w - __bfloat162float(h3));
    __nv_bfloat16* dh = g_hhi[0] + (size_t)idx * 4;
    __nv_bfloat16* dl = g_hlo[0] + (size_t)idx * 4;
    __nv_bfloat162 p;
    p.x = h0; p.y = h1; *(__nv_bfloat162*)(dh + 0) = p;
    p.x = h2; p.y = h3; *(__nv_bfloat162*)(dh + 2) = p;
    p.x = l0; p.y = l1; *(__nv_bfloat162*)(dl + 0) = p;
    p.x = l2; p.y = l3; *(__nv_bfloat162*)(dl + 2) = p;
}

// ---------------------------------------------------------------------------
// Step kernel: M=128 (batch) x N=64 (32 h-cols x {c,a}); K=1024 in 16 chunks
// of 64 bf16. cp.async 4-stage pipeline; grid (32, 2) = 64 CTAs x 256 thr.
// ---------------------------------------------------------------------------
#define KC       64
#define A_B      16384                 // 128 rows * 128B (per hi or lo)
#define B_B      8192                  // 64 rows * 128B
#define STG_B    (2 * A_B + 2 * B_B)   // 48 KB: Ahi|Alo|Bhi|Blo
#define OFF_AHI  0
#define OFF_ALO  16384
#define OFF_BHI  32768
#define OFF_BLO  40960
#define NSTG     4
#define DYN_SMEM (NSTG * STG_B + 1024) // +1KB for 1024B base alignment

__device__ __forceinline__ float fast_sig(float x) {
    return __fdividef(1.0f, 1.0f + __expf(-x));
}
__device__ __forceinline__ float fast_tanh(float x) {
    float e = __expf(2.0f * x);
    return 1.0f - __fdividef(2.0f, e + 1.0f);
}
__device__ __forceinline__ float nbrc_el(float cpre, float apre, float xh, float hp)
{
    float c = fast_sig(cpre);
    float a = 1.0f + fast_tanh(apre);
    return c * hp + (1.0f - c) * fast_tanh(xh + a * hp);
}

__device__ __forceinline__ void store_hilo(__nv_bfloat16* dh, __nv_bfloat16* dl, float4 o)
{
    __nv_bfloat16 h0 = __float2bfloat16(o.x), h1 = __float2bfloat16(o.y);
    __nv_bfloat16 h2 = __float2bfloat16(o.z), h3 = __float2bfloat16(o.w);
    __nv_bfloat16 l0 = __float2bfloat16(o.x - __bfloat162float(h0));
    __nv_bfloat16 l1 = __float2bfloat16(o.y - __bfloat162float(h1));
    __nv_bfloat16 l2 = __float2bfloat16(o.z - __bfloat162float(h2));
    __nv_bfloat16 l3 = __float2bfloat16(o.w - __bfloat162float(h3));
    __nv_bfloat162 p;
    p.x = h0; p.y = h1; *(__nv_bfloat162*)(dh + 0) = p;
    p.x = h2; p.y = h3; *(__nv_bfloat162*)(dh + 2) = p;
    p.x = l0; p.y = l1; *(__nv_bfloat162*)(dl + 0) = p;
    p.x = l2; p.y = l3; *(__nv_bfloat162*)(dl + 2) = p;
}

__global__ __launch_bounds__(256, 1) void step_mma(
    int t, int sbuf,
    const float* __restrict__ hprev,
    float* __restrict__ hout)
{
#if TC_OK
    extern __shared__ char dynraw[];
    __shared__ uint32_t s_tmem[1];
    __shared__ __align__(8) uint64_t s_mbar[NSTG];

    const int tid = threadIdx.x;
    const int wid = tid >> 5;
    const int m0  = blockIdx.y * 128;           // batch tile
    const int n0  = blockIdx.x * 64;            // Wcat row tile
    const int jh  = blockIdx.x * 32;            // h-column base

    // SW128 swizzle uses ABSOLUTE smem addr bits [9:7]: 1024B-align the base.
    const uint32_t rawb = smem_u32(dynraw);
    const uint32_t dynb = (rawb + 1023u) & ~1023u;

    const __nv_bfloat16* __restrict__ hhi = g_hhi[sbuf];
    const __nv_bfloat16* __restrict__ hlo = g_hlo[sbuf];
    __nv_bfloat16* __restrict__ nhhi = g_hhi[sbuf ^ 1];
    __nv_bfloat16* __restrict__ nhlo = g_hlo[sbuf ^ 1];

    uint32_t mb[NSTG];
    #pragma unroll
    for (int i = 0; i < NSTG; i++) mb[i] = smem_u32(&s_mbar[i]);

    if (wid == 0) tmem_alloc(smem_u32(s_tmem), 64);
    if (tid == 0) {
        #pragma unroll
        for (int i = 0; i < NSTG; i++) mbar_init(mb[i], 1);
    }
    __syncthreads();
    const uint32_t tmem = s_tmem[0];

    // load geometry: unit = (tid&7) 16B column group; rows r0 + 32i
    const int r0 = tid >> 3;                    // 0..31
    const int un = tid & 7;
    uint32_t swzA[4];
    #pragma unroll
    for (int i = 0; i < 4; i++)
        swzA[i] = SWZ((uint32_t)(r0 + 32 * i) * 128u + (uint32_t)un * 16u);

    const size_t acol = (size_t)un * 8;         // bf16 offset within row
    // issue one chunk's cp.asyncs into stage `sg`
    auto issue = [&](int c) {
        const int k0 = c * KC;
        const uint32_t sg = dynb + (c & (NSTG - 1)) * STG_B;
        #pragma unroll
        for (int i = 0; i < 4; i++) {
            size_t aofs = (size_t)(m0 + r0 + 32 * i) * H_ + k0 + acol;
            cp16(sg + OFF_AHI + swzA[i], hhi + aofs);
            cp16(sg + OFF_ALO + swzA[i], hlo + aofs);
        }
        #pragma unroll
        for (int i = 0; i < 2; i++) {
            size_t bofs = (size_t)(n0 + r0 + 32 * i) * H_ + k0 + acol;
            cp16(sg + OFF_BHI + swzA[i], g_Whi + bofs);
            cp16(sg + OFF_BLO + swzA[i], g_Wlo + bofs);
        }
    };

    // prefetch chunks 0..2
    issue(0); CP_COMMIT();
    issue(1); CP_COMMIT();
    issue(2); CP_COMMIT();

    uint32_t phbits = 0;
    #pragma unroll 1
    for (int c = 0; c < 16; c++) {
        CP_WAIT2();                 // chunk c's data resident
        fence_async_shared();
        __syncthreads();

        if (wid == 0 && elect1()) {
            const uint32_t sg = dynb + (c & (NSTG - 1)) * STG_B;
            uint64_t dah = smem_desc(sg + OFF_AHI);
            uint64_t dal = smem_desc(sg + OFF_ALO);
            uint64_t dbh = smem_desc(sg + OFF_BHI);
            uint64_t dbl = smem_desc(sg + OFF_BLO);
            #pragma unroll
            for (int s = 0; s < 4; s++) {      // 4 x K=16 per chunk
                mma_f16_ss(tmem, dah + 2 * s, dbh + 2 * s, IDESC64, (c | s) != 0);
                mma_f16_ss(tmem, dah + 2 * s, dbl + 2 * s, IDESC64, 1);
                mma_f16_ss(tmem, dal + 2 * s, dbh + 2 * s, IDESC64, 1);
            }
            tc_commit(mb[c & (NSTG - 1)]);
        }

        if (c >= 1) {               // release buffer of chunk c-1 (reused by c+3)
            const int ib = (c - 1) & (NSTG - 1);
            mbar_wait(mb[ib], (phbits >> ib) & 1u);
            phbits ^= 1u << ib;
        }
        if (c < 13) issue(c + 3);
        CP_COMMIT();                // empty groups keep wait_group 2 exact
    }

    // drain: chunk 15's MMA (in-order completion covers all earlier)
    mbar_wait(mb[3], (phbits >> 3) & 1u);
    tc_fence_after();

    // ---- epilogue: warp w -> rows of subpartition (w&3), col group (w>>2)
    {
        const int lane = tid & 31;
        const int sub  = wid & 3;
        const int cg   = wid >> 2;              // 0 or 1 (16 h-cols each)
        const int b    = m0 + sub * 32 + lane;

        uint32_t dc[16], da[16];
        tmem_ld16(dc, tmem + cg * 16);          // c preacts
        tmem_ld16(da, tmem + 32 + cg * 16);     // a preacts
        tc_wait_ld();
        tc_fence_before();

        const float* xrow = g_xall + (size_t)t * B_ * N3 + (size_t)b * N3;
        const int hb = jh + cg * 16;

        #pragma unroll
        for (int i = 0; i < 16; i += 4) {
            int hc = hb + i;
            float4 xc = *(const float4*)(xrow + hc);
            float4 xa = *(const float4*)(xrow + 1024 + hc);
            float4 xh = *(const float4*)(xrow + 2048 + hc);
            float4 hp = *(const float4*)(hprev + (size_t)b * H_ + hc);
            float4 o;
            o.x = nbrc_el(xc.x + __uint_as_float(dc[i + 0]), xa.x + __uint_as_float(da[i + 0]), xh.x, hp.x);
            o.y = nbrc_el(xc.y + __uint_as_float(dc[i + 1]), xa.y + __uint_as_float(da[i + 1]), xh.y, hp.y);
            o.z = nbrc_el(xc.z + __uint_as_float(dc[i + 2]), xa.z + __uint_as_float(da[i + 2]), xh.z, hp.z);
            o.w = nbrc_el(xc.w + __uint_as_float(dc[i + 3]), xa.w + __uint_as_float(da[i + 3]), xh.w, hp.w);
            *(float4*)(hout + (size_t)b * H_ + hc) = o;
            store_hilo(nhhi + (size_t)b * H_ + hc, nhlo + (size_t)b * H_ + hc, o);
        }
    }

    __syncthreads();
    if (tid == 0) {
        #pragma unroll
        for (int i = 0; i < NSTG; i++) mbar_inval(mb[i]);
    }
    __syncthreads();
    if (wid == 0) {
        tmem_relinquish();
        tmem_dealloc(tmem, 64);
    }
#else
    // ---- SIMT fallback (plain compute_103 pass; never selected on GB300) ----
    const int tid = threadIdx.x;
    const int m0  = blockIdx.y * 128;
    const int n0  = blockIdx.x * 64;
    const int jh  = blockIdx.x * 32;
    const int sbx = sbuf ^ 1;

    const int b    = m0 + (tid >> 1);
    const int half = tid & 1;

    const float* xrow = g_xall + (size_t)t * B_ * N3 + (size_t)b * N3;
    for (int jj = 0; jj < 16; jj++) {
        const int j    = half * 16 + jj;
        const int hc   = jh + j;
        const int rowc = n0 + j;
        const int rowa = n0 + 32 + j;
        float sc = 0.f, sa = 0.f;
        const float* hp = hprev + (size_t)b * H_;
        for (int k = 0; k < H_; k++) {
            float wc = __bfloat162float(g_Whi[(size_t)rowc * H_ + k]) +
                       __bfloat162float(g_Wlo[(size_t)rowc * H_ + k]);
            float wa = __bfloat162float(g_Whi[(size_t)rowa * H_ + k]) +
                       __bfloat162float(g_Wlo[(size_t)rowa * H_ + k]);
            sc += hp[k] * wc;
            sa += hp[k] * wa;
        }
        float hpv = hprev[(size_t)b * H_ + hc];
        float o = nbrc_el(xrow[hc] + sc, xrow[1024 + hc] + sa, xrow[2048 + hc], hpv);
        hout[(size_t)b * H_ + hc] = o;
        __nv_bfloat16 hi = __float2bfloat16(o);
        __nv_bfloat16 lo = __float2bfloat16(o - __bfloat162float(hi));
        g_hhi[sbx][(size_t)b * H_ + hc] = hi;
        g_hlo[sbx][(size_t)b * H_ + hc] = lo;
    }
#endif
}

// ---------------------------------------------------------------------------
extern "C" void kernel_launch(void* const* d_in, const int* in_sizes, int n_in,
                              void* d_out, int out_size)
{
    const float* x   = (const float*)d_in[0];
    const float* h0i = (const float*)d_in[1];
    const float* Uc  = (const float*)d_in[2];
    const float* Wc  = (const float*)d_in[3];
    const float* bc  = (const float*)d_in[4];
    const float* Ua  = (const float*)d_in[5];
    const float* Wa  = (const float*)d_in[6];
    const float* ba  = (const float*)d_in[7];
    const float* Uh  = (const float*)d_in[8];
    float* out = (float*)d_out;

    cudaFuncSetAttribute(step_mma, cudaFuncAttributeMaxDynamicSharedMemorySize, DYN_SMEM);

    pack_w<<<2048, 256>>>(Wc, Wa);
    conv_h0<<<256, 256>>>(h0i);

    dim3 pgrid(N3 / 128, M_ / 128);
    proj_kernel<<<pgrid, 256>>>(x, Uc, Ua, Uh, bc, ba);

    dim3 sgrid(32, 2);
    for (int t = 0; t < T_; t++) {
        const float* hp = (t == 0) ? h0i : out + (size_t)(t - 1) * B_ * H_;
        step_mma<<<sgrid, 256, DYN_SMEM>>>(t, t & 1, hp, out + (size_t)t * B_ * H_);
    }

    cudaMemcpyAsync(out + (size_t)T_ * B_ * H_,
                    out + (size_t)(T_ - 1) * B_ * H_,
                    (size_t)B_ * H_ * sizeof(float),
                    cudaMemcpyDeviceToDevice);
}